// round 10
// baseline (speedup 1.0000x reference)
#include <cuda_runtime.h>

#define T_LEN 2048
typedef unsigned long long u64;

// ---- MUFU.TANH (1 MUFU per activation) ----
__device__ __forceinline__ float tanha(float x){ float y; asm("tanh.approx.f32 %0, %1;" : "=f"(y) : "f"(x)); return y; }

// ---- packed f32x2 helpers (sm_100+) ----
__device__ __forceinline__ u64 pk(float lo, float hi){ u64 d; asm("mov.b64 %0, {%1, %2};" : "=l"(d) : "f"(lo), "f"(hi)); return d; }
__device__ __forceinline__ void unpk(u64 d, float& lo, float& hi){ asm("mov.b64 {%0, %1}, %2;" : "=f"(lo), "=f"(hi) : "l"(d)); }
__device__ __forceinline__ u64 fma2_(u64 a, u64 b, u64 c){ u64 d; asm("fma.rn.f32x2 %0, %1, %2, %3;" : "=l"(d) : "l"(a), "l"(b), "l"(c)); return d; }
__device__ __forceinline__ u64 mul2_(u64 a, u64 b){ u64 d; asm("mul.rn.f32x2 %0, %1, %2;" : "=l"(d) : "l"(a), "l"(b)); return d; }
__device__ __forceinline__ u64 add2_(u64 a, u64 b){ u64 d; asm("add.rn.f32x2 %0, %1, %2;" : "=l"(d) : "l"(a), "l"(b)); return d; }

// Activation on pre-scaled preacts (sigmoid rows x0.5; h carried as 2h with
// the extra 0.5 folded into h-consuming weights). Returns 2h; updates c.
__device__ __forceinline__ float lstm_act(float a_i, float a_f, float a_g, float a_o, float& c) {
    const float thi = tanha(a_i), thf = tanha(a_f);
    const float thg = tanha(a_g), tho = tanha(a_o);
    const float F  = fmaf(0.5f, thf, 0.5f);
    const float g2 = fmaf(thi, thg, thg);           // 2*sigmoid(i)*tanh(g)
    c = fmaf(F, c, 0.5f * g2);
    const float thc = tanha(c);
    return fmaf(tho, thc, thc);                      // 2*sigmoid(o)*tanh(c)
}

// DUAL-BATCH: each thread runs TWO independent sequences (batch pair),
// interleaved at instruction level — ILP replaces the occupancy this
// problem cannot provide. Weights (the big register cost) are shared.
// 8 lanes per batch pair; lane j owns unit j of both layers for BOTH
// batches. h exchange via padded SMEM, double-buffered, 1 syncwarp/step.
// block=128, grid=B/32 -> 1 warp per SMSP uniformly.
__global__ void __launch_bounds__(128) lstm2_dual_kernel(
    const float* __restrict__ x,
    const float* __restrict__ w_ih1, const float* __restrict__ w_hh1,
    const float* __restrict__ b_ih1, const float* __restrict__ b_hh1,
    const float* __restrict__ w_ih2, const float* __restrict__ w_hh2,
    const float* __restrict__ b_ih2, const float* __restrict__ b_hh2,
    const float* __restrict__ fc_w, const float* __restrict__ fc_b,
    float* __restrict__ out, int B)
{
    const int tid  = blockIdx.x * blockDim.x + threadIdx.x;
    const int pidx = tid >> 3;                 // batch-pair index
    if (pidx >= (B >> 1)) return;
    const int j    = tid & 7;
    const int bA   = pidx * 2, bB = bA + 1;

    const int gi = j, gf = j + 8, gg = j + 16, go = j + 24;

    // fold: sigmoid rows x0.5; h-consuming weights an extra x0.5 (h is 2h)
    const float SH = 0.25f, TH = 0.5f, SX = 0.5f, TX = 1.0f;

    u64 whIF1[8], whGO1[8], wxIF2[8], wxGO2[8], whIF2[8], whGO2[8];
    #pragma unroll
    for (int k = 0; k < 8; k++) {
        whIF1[k] = pk(SH * w_hh1[gi*8+k], SH * w_hh1[gf*8+k]);
        whGO1[k] = pk(TH * w_hh1[gg*8+k], SH * w_hh1[go*8+k]);
        wxIF2[k] = pk(SH * w_ih2[gi*8+k], SH * w_ih2[gf*8+k]);
        wxGO2[k] = pk(TH * w_ih2[gg*8+k], SH * w_ih2[go*8+k]);
        whIF2[k] = pk(SH * w_hh2[gi*8+k], SH * w_hh2[gf*8+k]);
        whGO2[k] = pk(TH * w_hh2[gg*8+k], SH * w_hh2[go*8+k]);
    }
    const u64 wx1IF = pk(SX * w_ih1[gi], SX * w_ih1[gf]);
    const u64 wx1GO = pk(TX * w_ih1[gg], SX * w_ih1[go]);
    const u64 bIF1  = pk(SX*(b_ih1[gi]+b_hh1[gi]), SX*(b_ih1[gf]+b_hh1[gf]));
    const u64 bGO1  = pk(TX*(b_ih1[gg]+b_hh1[gg]), SX*(b_ih1[go]+b_hh1[go]));
    const u64 bIF2  = pk(SX*(b_ih2[gi]+b_hh2[gi]), SX*(b_ih2[gf]+b_hh2[gf]));
    const u64 bGO2  = pk(TX*(b_ih2[gg]+b_hh2[gg]), SX*(b_ih2[go]+b_hh2[go]));

    // ---- SMEM h-exchange: [pair-member][parity][group][H1 0..7 | H2 8..15] pad 17 ----
    __shared__ __align__(16) u64 hb[2][2][16][17];
    const int grp = threadIdx.x >> 3;          // pair-group within CTA (0..15)

    float c1[2] = {0.f, 0.f}, c2[2] = {0.f, 0.f};

    const float* xbA = x + (size_t)bA * T_LEN;
    const float* xbB = x + (size_t)bB * T_LEN;

    // ---- prologue (t=0): L1 step 0 for both batches; h2(-1)=0; parity 0 ----
    {
        const float x0A = __ldg(&xbA[0]), x0B = __ldg(&xbB[0]);
        const float xv[2] = {x0A, x0B};
        #pragma unroll
        for (int pb = 0; pb < 2; pb++) {
            float ai, af, ag, ao;
            unpk(fma2_(wx1IF, pk(xv[pb], xv[pb]), bIF1), ai, af);
            unpk(fma2_(wx1GO, pk(xv[pb], xv[pb]), bGO1), ag, ao);
            const float h1x = lstm_act(ai, af, ag, ao, c1[pb]);
            float* s1 = (float*)&hb[pb][0][grp][j];
            float* s2 = (float*)&hb[pb][0][grp][8 + j];
            s1[0] = h1x; s1[1] = h1x;
            s2[0] = 0.f; s2[1] = 0.f;
        }
        __syncwarp();
    }

    float xnA = __ldg(&xbA[1]), xnB = __ldg(&xbB[1]);

    // ---- main loop: iteration t computes L1(t) and L2(t-1) for both batches ----
    #pragma unroll 1
    for (int t = 1; t < T_LEN; t++) {
        const float xA = xnA, xB = xnB;
        const int tn = (t + 1) & (T_LEN - 1);          // wraps harmlessly
        xnA = __ldg(&xbA[tn]);
        xnB = __ldg(&xbB[tn]);
        const int q = (t - 1) & 1, p = t & 1;

        u64 XT[2]; XT[0] = pk(xA, xA); XT[1] = pk(xB, xB);

        // load h vectors (duplicated-packed) for both batches
        u64 H1[2][8], H2[2][8];
        #pragma unroll
        for (int pb = 0; pb < 2; pb++) {
            const u64* hv = &hb[pb][q][grp][0];
            #pragma unroll
            for (int k = 0; k < 8; k++) { H1[pb][k] = hv[k]; H2[pb][k] = hv[8 + k]; }
        }

        // L1(t) pre-acts: 8 interleaved chains (4 per batch)
        u64 aIF0[2], aGO0[2], aIF1[2], aGO1[2];
        #pragma unroll
        for (int pb = 0; pb < 2; pb++) {
            aIF0[pb] = fma2_(wx1IF, XT[pb], bIF1);
            aGO0[pb] = fma2_(wx1GO, XT[pb], bGO1);
        }
        #pragma unroll
        for (int k = 0; k < 4; k++)
            #pragma unroll
            for (int pb = 0; pb < 2; pb++) {
                aIF0[pb] = fma2_(whIF1[k], H1[pb][k], aIF0[pb]);
                aGO0[pb] = fma2_(whGO1[k], H1[pb][k], aGO0[pb]);
            }
        #pragma unroll
        for (int pb = 0; pb < 2; pb++) {
            aIF1[pb] = mul2_(whIF1[4], H1[pb][4]);
            aGO1[pb] = mul2_(whGO1[4], H1[pb][4]);
        }
        #pragma unroll
        for (int k = 5; k < 8; k++)
            #pragma unroll
            for (int pb = 0; pb < 2; pb++) {
                aIF1[pb] = fma2_(whIF1[k], H1[pb][k], aIF1[pb]);
                aGO1[pb] = fma2_(whGO1[k], H1[pb][k], aGO1[pb]);
            }

        // L2(t-1) pre-acts: 8 interleaved chains
        u64 eIF0[2], eGO0[2], eIF1[2], eGO1[2];
        #pragma unroll
        for (int pb = 0; pb < 2; pb++) { eIF0[pb] = bIF2; eGO0[pb] = bGO2; }
        #pragma unroll
        for (int k = 0; k < 8; k++)
            #pragma unroll
            for (int pb = 0; pb < 2; pb++) {
                eIF0[pb] = fma2_(whIF2[k], H2[pb][k], eIF0[pb]);
                eGO0[pb] = fma2_(whGO2[k], H2[pb][k], eGO0[pb]);
            }
        #pragma unroll
        for (int pb = 0; pb < 2; pb++) {
            eIF1[pb] = mul2_(wxIF2[0], H1[pb][0]);
            eGO1[pb] = mul2_(wxGO2[0], H1[pb][0]);
        }
        #pragma unroll
        for (int k = 1; k < 8; k++)
            #pragma unroll
            for (int pb = 0; pb < 2; pb++) {
                eIF1[pb] = fma2_(wxIF2[k], H1[pb][k], eIF1[pb]);
                eGO1[pb] = fma2_(wxGO2[k], H1[pb][k], eGO1[pb]);
            }

        // ---- activations (two independent scalar chains interleave) ----
        #pragma unroll
        for (int pb = 0; pb < 2; pb++) {
            float a_i, a_f, a_g, a_o;
            unpk(add2_(aIF0[pb], aIF1[pb]), a_i, a_f);
            unpk(add2_(aGO0[pb], aGO1[pb]), a_g, a_o);
            const float h1x = lstm_act(a_i, a_f, a_g, a_o, c1[pb]);

            float e_i, e_f, e_g, e_o;
            unpk(add2_(eIF0[pb], eIF1[pb]), e_i, e_f);
            unpk(add2_(eGO0[pb], eGO1[pb]), e_g, e_o);
            const float h2x = lstm_act(e_i, e_f, e_g, e_o, c2[pb]);

            float* s1 = (float*)&hb[pb][p][grp][j];
            float* s2 = (float*)&hb[pb][p][grp][8 + j];
            s1[0] = h1x; s1[1] = h1x;
            s2[0] = h2x; s2[1] = h2x;
        }
        __syncwarp();
    }

    // ---- epilogue: L2(T-1) for both batches; last store was parity 1 ----
    float h2last[2];
    #pragma unroll
    for (int pb = 0; pb < 2; pb++) {
        const u64* hv = &hb[pb][1][grp][0];
        u64 H1[8], H2[8];
        #pragma unroll
        for (int k = 0; k < 8; k++) { H1[k] = hv[k]; H2[k] = hv[8 + k]; }

        u64 eIF0 = bIF2, eGO0 = bGO2;
        #pragma unroll
        for (int k = 0; k < 8; k++) {
            eIF0 = fma2_(whIF2[k], H2[k], eIF0);
            eGO0 = fma2_(whGO2[k], H2[k], eGO0);
        }
        u64 eIF1 = mul2_(wxIF2[0], H1[0]);
        u64 eGO1 = mul2_(wxGO2[0], H1[0]);
        #pragma unroll
        for (int k = 1; k < 8; k++) {
            eIF1 = fma2_(wxIF2[k], H1[k], eIF1);
            eGO1 = fma2_(wxGO2[k], H1[k], eGO1);
        }
        float e_i, e_f, e_g, e_o;
        unpk(add2_(eIF0, eIF1), e_i, e_f);
        unpk(add2_(eGO0, eGO1), e_g, e_o);
        h2last[pb] = lstm_act(e_i, e_f, e_g, e_o, c2[pb]);
    }

    // ---- fc: publish final h2 (as 2h) through SMEM, lanes j<4 write both outs ----
    {
        ((float*)&hb[0][0][grp][j])[0] = h2last[0];
        ((float*)&hb[1][0][grp][j])[0] = h2last[1];
        __syncwarp();
        if (j < 4) {
            float accA = fc_b[j], accB = fc_b[j];
            #pragma unroll
            for (int k = 0; k < 8; k++) {
                const float w = 0.5f * fc_w[j*8+k];    // h stored as 2h
                accA = fmaf(w, ((const float*)&hb[0][0][grp][k])[0], accA);
                accB = fmaf(w, ((const float*)&hb[1][0][grp][k])[0], accB);
            }
            out[bA*4 + j] = accA;
            out[bB*4 + j] = accB;
        }
    }
}

extern "C" void kernel_launch(void* const* d_in, const int* in_sizes, int n_in,
                              void* d_out, int out_size)
{
    const float* x     = (const float*)d_in[0];
    const float* w_ih1 = (const float*)d_in[1];
    const float* w_hh1 = (const float*)d_in[2];
    const float* b_ih1 = (const float*)d_in[3];
    const float* b_hh1 = (const float*)d_in[4];
    const float* w_ih2 = (const float*)d_in[5];
    const float* w_hh2 = (const float*)d_in[6];
    const float* b_ih2 = (const float*)d_in[7];
    const float* b_hh2 = (const float*)d_in[8];
    const float* fc_w  = (const float*)d_in[9];
    const float* fc_b  = (const float*)d_in[10];
    float* out = (float*)d_out;

    const int B = in_sizes[0] / T_LEN;        // 4096
    const int threads = (B / 2) * 8;          // 16384 -> 512 warps
    const int block = 128;                    // 128 CTAs -> 1 warp/SMSP uniform
    const int grid = (threads + block - 1) / block;

    lstm2_dual_kernel<<<grid, block>>>(x, w_ih1, w_hh1, b_ih1, b_hh1,
                                       w_ih2, w_hh2, b_ih2, b_hh2,
                                       fc_w, fc_b, out, B);
}

// round 11
// speedup vs baseline: 2.1801x; 2.1801x over previous
#include <cuda_runtime.h>

#define T_LEN 2048
typedef unsigned long long u64;

// ---- MUFU.TANH (1 MUFU per activation) ----
__device__ __forceinline__ float tanha(float x){ float y; asm("tanh.approx.f32 %0, %1;" : "=f"(y) : "f"(x)); return y; }

// ---- packed f32x2 helpers (sm_100+) ----
__device__ __forceinline__ u64 pk(float lo, float hi){ u64 d; asm("mov.b64 %0, {%1, %2};" : "=l"(d) : "f"(lo), "f"(hi)); return d; }
__device__ __forceinline__ void unpk(u64 d, float& lo, float& hi){ asm("mov.b64 {%0, %1}, %2;" : "=f"(lo), "=f"(hi) : "l"(d)); }
__device__ __forceinline__ u64 fma2_(u64 a, u64 b, u64 c){ u64 d; asm("fma.rn.f32x2 %0, %1, %2, %3;" : "=l"(d) : "l"(a), "l"(b), "l"(c)); return d; }
__device__ __forceinline__ u64 mul2_(u64 a, u64 b){ u64 d; asm("mul.rn.f32x2 %0, %1, %2;" : "=l"(d) : "l"(a), "l"(b)); return d; }
__device__ __forceinline__ u64 add2_(u64 a, u64 b){ u64 d; asm("add.rn.f32x2 %0, %1, %2;" : "=l"(d) : "l"(a), "l"(b)); return d; }

// Activation on pre-scaled preacts (sigmoid rows x0.5; h carried as 2h with
// the extra 0.5 folded into h-consuming weights). Returns 2h; updates c.
__device__ __forceinline__ float lstm_act(float a_i, float a_f, float a_g, float a_o, float& c) {
    const float thi = tanha(a_i), thf = tanha(a_f);
    const float thg = tanha(a_g), tho = tanha(a_o);
    const float F  = fmaf(0.5f, thf, 0.5f);
    const float g2 = fmaf(thi, thg, thg);           // 2*sigmoid(i)*tanh(g)
    c = fmaf(F, c, 0.5f * g2);
    const float thc = tanha(c);
    return fmaf(tho, thc, thc);                      // 2*sigmoid(o)*tanh(c)
}

// R8 layout (best known): 8 lanes per batch; lane j owns gate rows
// {j, j+8, j+16, j+24} of both layers, packed (i,f)/(g,o). Layers
// software-pipelined: iteration t computes L1(t) and L2(t-1).
// R10 diet vs R8:
//  * group rows padded to 18 u64 (144 B, 16B-aligned) -> H1/H2 reloaded with
//    8 LDS.128 instead of 16 LDS.64 (conflict-free across the 4 groups).
//  * h1x stored to SMEM immediately, before the L2 activation tower.
__global__ void __launch_bounds__(128) lstm2_fused_kernel(
    const float* __restrict__ x,
    const float* __restrict__ w_ih1, const float* __restrict__ w_hh1,
    const float* __restrict__ b_ih1, const float* __restrict__ b_hh1,
    const float* __restrict__ w_ih2, const float* __restrict__ w_hh2,
    const float* __restrict__ b_ih2, const float* __restrict__ b_hh2,
    const float* __restrict__ fc_w, const float* __restrict__ fc_b,
    float* __restrict__ out, int B)
{
    const int tid = blockIdx.x * blockDim.x + threadIdx.x;
    const int b   = tid >> 3;
    if (b >= B) return;
    const int j   = tid & 7;
    const unsigned FULL = 0xffffffffu;

    const int gi = j, gf = j + 8, gg = j + 16, go = j + 24;

    // fold: sigmoid rows x0.5; h-consuming weights an extra x0.5 (h is 2h)
    const float SH = 0.25f, TH = 0.5f, SX = 0.5f, TX = 1.0f;

    u64 whIF1[8], whGO1[8], wxIF2[8], wxGO2[8], whIF2[8], whGO2[8];
    #pragma unroll
    for (int k = 0; k < 8; k++) {
        whIF1[k] = pk(SH * w_hh1[gi*8+k], SH * w_hh1[gf*8+k]);
        whGO1[k] = pk(TH * w_hh1[gg*8+k], SH * w_hh1[go*8+k]);
        wxIF2[k] = pk(SH * w_ih2[gi*8+k], SH * w_ih2[gf*8+k]);
        wxGO2[k] = pk(TH * w_ih2[gg*8+k], SH * w_ih2[go*8+k]);
        whIF2[k] = pk(SH * w_hh2[gi*8+k], SH * w_hh2[gf*8+k]);
        whGO2[k] = pk(TH * w_hh2[gg*8+k], SH * w_hh2[go*8+k]);
    }
    const u64 wx1IF = pk(SX * w_ih1[gi], SX * w_ih1[gf]);
    const u64 wx1GO = pk(TX * w_ih1[gg], SX * w_ih1[go]);
    const u64 bIF1  = pk(SX*(b_ih1[gi]+b_hh1[gi]), SX*(b_ih1[gf]+b_hh1[gf]));
    const u64 bGO1  = pk(TX*(b_ih1[gg]+b_hh1[gg]), SX*(b_ih1[go]+b_hh1[go]));
    const u64 bIF2  = pk(SX*(b_ih2[gi]+b_hh2[gi]), SX*(b_ih2[gf]+b_hh2[gf]));
    const u64 bGO2  = pk(TX*(b_ih2[gg]+b_hh2[gg]), SX*(b_ih2[go]+b_hh2[go]));

    // ---- SMEM h-exchange: [parity][group][H1 0..7 | H2 8..15 | pad], stride 18 ----
    __shared__ __align__(16) u64 hb[2][16][18];
    const int grp = threadIdx.x >> 3;         // group within CTA (0..15)

    float c1 = 0.0f, c2 = 0.0f;

    const float* xb = x + (size_t)b * T_LEN;

    // ---- prologue (t=0): L1 step 0 (h1=c1=0); h2(-1)=0. Writes parity 0 ----
    {
        const float x0 = __ldg(&xb[0]);
        float ai, af, ag, ao;
        unpk(fma2_(wx1IF, pk(x0, x0), bIF1), ai, af);
        unpk(fma2_(wx1GO, pk(x0, x0), bGO1), ag, ao);
        const float h1x = lstm_act(ai, af, ag, ao, c1);
        float* s1 = (float*)&hb[0][grp][j];
        float* s2 = (float*)&hb[0][grp][8 + j];
        s1[0] = h1x; s1[1] = h1x;
        s2[0] = 0.f; s2[1] = 0.f;
        __syncwarp();
    }

    float xt_next = __ldg(&xb[1]);

    // ---- main loop: iteration t computes L1(t) and L2(t-1) ----
    #pragma unroll 2
    for (int t = 1; t < T_LEN; t++) {
        const float xt = xt_next;
        xt_next = __ldg(&xb[(t + 1) & (T_LEN - 1)]);   // wraps harmlessly
        const int q = (t - 1) & 1, p = t & 1;

        // reload h vectors with 8x LDS.128 (rows are 16B-aligned, stride 144B)
        u64 H1[8], H2[8];
        {
            const ulonglong2* hv = (const ulonglong2*)&hb[q][grp][0];
            #pragma unroll
            for (int m = 0; m < 4; m++) { ulonglong2 v = hv[m];     H1[2*m] = v.x; H1[2*m+1] = v.y; }
            #pragma unroll
            for (int m = 0; m < 4; m++) { ulonglong2 v = hv[4 + m]; H2[2*m] = v.x; H2[2*m+1] = v.y; }
        }

        const u64 XT = pk(xt, xt);

        // L1(t) pre-acts: b1 + wx1*x + wh1 . H1 (two parallel 4/5-chains)
        u64 aIF0 = fma2_(wx1IF, XT, bIF1);
        u64 aGO0 = fma2_(wx1GO, XT, bGO1);
        #pragma unroll
        for (int k = 0; k < 4; k++) {
            aIF0 = fma2_(whIF1[k], H1[k], aIF0);
            aGO0 = fma2_(whGO1[k], H1[k], aGO0);
        }
        u64 aIF1 = mul2_(whIF1[4], H1[4]);
        u64 aGO1 = mul2_(whGO1[4], H1[4]);
        #pragma unroll
        for (int k = 5; k < 8; k++) {
            aIF1 = fma2_(whIF1[k], H1[k], aIF1);
            aGO1 = fma2_(whGO1[k], H1[k], aGO1);
        }

        // L2(t-1) pre-acts: b2 + wh2 . H2 + wx2 . H1 (two parallel 8-chains)
        u64 eIF0 = bIF2, eGO0 = bGO2;
        #pragma unroll
        for (int k = 0; k < 8; k++) {
            eIF0 = fma2_(whIF2[k], H2[k], eIF0);
            eGO0 = fma2_(whGO2[k], H2[k], eGO0);
        }
        u64 eIF1 = mul2_(wxIF2[0], H1[0]);
        u64 eGO1 = mul2_(wxGO2[0], H1[0]);
        #pragma unroll
        for (int k = 1; k < 8; k++) {
            eIF1 = fma2_(wxIF2[k], H1[k], eIF1);
            eGO1 = fma2_(wxGO2[k], H1[k], eGO1);
        }

        // ---- L1 activation, store h1x IMMEDIATELY (overlaps with L2 acts) ----
        float a_i, a_f, a_g, a_o;
        unpk(add2_(aIF0, aIF1), a_i, a_f);
        unpk(add2_(aGO0, aGO1), a_g, a_o);
        const float h1x = lstm_act(a_i, a_f, a_g, a_o, c1);
        float* s1 = (float*)&hb[p][grp][j];
        s1[0] = h1x; s1[1] = h1x;

        // ---- L2 activation ----
        float e_i, e_f, e_g, e_o;
        unpk(add2_(eIF0, eIF1), e_i, e_f);
        unpk(add2_(eGO0, eGO1), e_g, e_o);
        const float h2x = lstm_act(e_i, e_f, e_g, e_o, c2);
        float* s2 = (float*)&hb[p][grp][8 + j];
        s2[0] = h2x; s2[1] = h2x;

        __syncwarp();
    }

    // ---- epilogue: L2(T-1). Last store was parity 1 ----
    float h2last;
    {
        u64 H1[8], H2[8];
        const ulonglong2* hv = (const ulonglong2*)&hb[1][grp][0];
        #pragma unroll
        for (int m = 0; m < 4; m++) { ulonglong2 v = hv[m];     H1[2*m] = v.x; H1[2*m+1] = v.y; }
        #pragma unroll
        for (int m = 0; m < 4; m++) { ulonglong2 v = hv[4 + m]; H2[2*m] = v.x; H2[2*m+1] = v.y; }

        u64 eIF0 = bIF2, eGO0 = bGO2;
        #pragma unroll
        for (int k = 0; k < 8; k++) {
            eIF0 = fma2_(whIF2[k], H2[k], eIF0);
            eGO0 = fma2_(whGO2[k], H2[k], eGO0);
        }
        u64 eIF1 = mul2_(wxIF2[0], H1[0]);
        u64 eGO1 = mul2_(wxGO2[0], H1[0]);
        #pragma unroll
        for (int k = 1; k < 8; k++) {
            eIF1 = fma2_(wxIF2[k], H1[k], eIF1);
            eGO1 = fma2_(wxGO2[k], H1[k], eGO1);
        }
        float e_i, e_f, e_g, e_o;
        unpk(add2_(eIF0, eIF1), e_i, e_f);
        unpk(add2_(eGO0, eGO1), e_g, e_o);
        h2last = lstm_act(e_i, e_f, e_g, e_o, c2);    // h2x of final step
    }

    // ---- fc on final h2 (h stored as 2h -> fc_w pre-halved) ----
    float h2f[8];
    #pragma unroll
    for (int k = 0; k < 8; k++) h2f[k] = __shfl_sync(FULL, h2last, k, 8);
    if (j < 4) {
        float acc = fc_b[j];
        #pragma unroll
        for (int k = 0; k < 8; k++) acc = fmaf(0.5f * fc_w[j*8+k], h2f[k], acc);
        out[b*4 + j] = acc;
    }
}

extern "C" void kernel_launch(void* const* d_in, const int* in_sizes, int n_in,
                              void* d_out, int out_size)
{
    const float* x     = (const float*)d_in[0];
    const float* w_ih1 = (const float*)d_in[1];
    const float* w_hh1 = (const float*)d_in[2];
    const float* b_ih1 = (const float*)d_in[3];
    const float* b_hh1 = (const float*)d_in[4];
    const float* w_ih2 = (const float*)d_in[5];
    const float* w_hh2 = (const float*)d_in[6];
    const float* b_ih2 = (const float*)d_in[7];
    const float* b_hh2 = (const float*)d_in[8];
    const float* fc_w  = (const float*)d_in[9];
    const float* fc_b  = (const float*)d_in[10];
    float* out = (float*)d_out;

    const int B = in_sizes[0] / T_LEN;      // 4096
    const int threads = B * 8;              // 8 lanes per batch element
    const int block = 128;                  // best-known config
    const int grid = (threads + block - 1) / block;

    lstm2_fused_kernel<<<grid, block>>>(x, w_ih1, w_hh1, b_ih1, b_hh1,
                                        w_ih2, w_hh2, b_ih2, b_hh2,
                                        fc_w, fc_b, out, B);
}